// round 15
// baseline (speedup 1.0000x reference)
#include <cuda_runtime.h>
#include <cuda_fp16.h>
#include <cstddef>
#include <cstdint>

#define BB 4
#define NN 4096
#define KK 16
#define DP 64
#define DM 256
#define NPTS (BB*NN)
#define MTOT (NPTS*KK)

// ---------------- device-global scratch (no allocs allowed) ----------------
__device__ __half g_Wposth[DP*DM];   // [n=64][k=256]
__device__ __half g_Wpreh[DM*DP];    // [n=256][k=64]
__device__ __half g_WQh [DM*DM];     // [n][k]
__device__ __half g_WKh [DM*DM];
__device__ __half g_WVh [DM*DM];
__device__ __half g_Wprojh[DM*DM];
__device__ __half g_Wp2h[DM*DM];
__device__ __half g_Wa1h[DM*DM];
__device__ __half g_Wa2h[DM*DM];
__device__ __half g_Qh [NPTS*DM];
__device__ __half g_Kh [NPTS*DM];
__device__ __half g_Vh [NPTS*DM];
__device__ int   g_idx[NPTS*KK];
__device__ __half g_resh[(size_t)NPTS*DM];

// ---------------- helpers ----------------
__device__ __forceinline__ uint32_t smem_u32(const void* p) {
    uint32_t a;
    asm("{ .reg .u64 t; cvta.to.shared.u64 t, %1; cvt.u32.u64 %0, t; }" : "=r"(a) : "l"(p));
    return a;
}
#define CP16(dst, src) asm volatile("cp.async.cg.shared.global [%0], [%1], 16;" :: "r"(dst), "l"(src) : "memory")
#define CP_COMMIT()    asm volatile("cp.async.commit_group;" ::: "memory")
#define CP_WAIT1()     asm volatile("cp.async.wait_group 1;" ::: "memory")
#define CP_WAIT0()     asm volatile("cp.async.wait_group 0;" ::: "memory")
#define LDSM4(r0,r1,r2,r3,a) \
    asm volatile("ldmatrix.sync.aligned.m8n8.x4.shared.b16 {%0,%1,%2,%3}, [%4];" \
                 : "=r"(r0),"=r"(r1),"=r"(r2),"=r"(r3) : "r"(a))

__device__ __forceinline__ void mma16816(float* c, const uint32_t* a, uint32_t b0, uint32_t b1) {
    asm volatile("mma.sync.aligned.m16n8k16.row.col.f32.f16.f16.f32 "
        "{%0,%1,%2,%3}, {%4,%5,%6,%7}, {%8,%9}, {%0,%1,%2,%3};"
        : "+f"(c[0]), "+f"(c[1]), "+f"(c[2]), "+f"(c[3])
        : "r"(a[0]), "r"(a[1]), "r"(a[2]), "r"(a[3]), "r"(b0), "r"(b1));
}

#define APITCH_B 528
#define ABYTES128 (128*APITCH_B)           // 67584
#define BBYTES    (256*144)                // 36864
#define QKV_SMEM  (ABYTES128 + 2*BBYTES)   // 141312 (qkvmma + finalmma)
#define UOFF      ABYTES128
#define BOFF      (2*ABYTES128)
#define MEGA_SMEM (2*ABYTES128 + 2*BBYTES) // 208896

// ---------------- weight prep ----------------
__global__ void prep_kernel(const float* __restrict__ W_pre,
                            const float* __restrict__ WQ,  const float* __restrict__ WK,
                            const float* __restrict__ WV,  const float* __restrict__ Wproj,
                            const float* __restrict__ W_post,
                            const float* __restrict__ Wp2, const float* __restrict__ Wa1,
                            const float* __restrict__ Wa2)
{
    int t = blockIdx.x * blockDim.x + threadIdx.x;
    if (t < DM*DP) {
        g_Wpreh[t]  = __float2half_rn(W_pre[t]);
        g_Wposth[t] = __float2half_rn(W_post[t]);
    }
    if (t < DM*DM) {
        g_WQh  [t] = __float2half_rn(WQ[t]);
        g_WKh  [t] = __float2half_rn(WK[t]);
        g_WVh  [t] = __float2half_rn(WV[t]);
        g_Wprojh[t] = __float2half_rn(Wproj[t]);
        g_Wp2h[t] = __float2half_rn(Wp2[t]);
        g_Wa1h[t] = __float2half_rn(Wa1[t]);
        g_Wa2h[t] = __float2half_rn(Wa2[t]);
    }
}

// ---------------- kNN v3 (batch-offset param) ----------------
__device__ __forceinline__ void ins16(float* bd, int* bi, float d, int m)
{
    #pragma unroll
    for (int i = 15; i >= 1; i--) {
        bool c1 = d < bd[i-1];
        bool c2 = d < bd[i];
        float nb = c1 ? bd[i-1] : (c2 ? d : bd[i]);
        int   ni = c1 ? bi[i-1] : (c2 ? m : bi[i]);
        bd[i] = nb; bi[i] = ni;
    }
    if (d < bd[0]) { bi[0] = m; bd[0] = d; }
}

__global__ void __launch_bounds__(256) knn_kernel(const float* __restrict__ xyz, int bbase)
{
    extern __shared__ float4 pts[];
    __shared__ float md[64][3][16];
    __shared__ int   mi[64][3][16];

    int b     = bbase + (blockIdx.x >> 6);
    int chunk = blockIdx.x & 63;
    const float* xb = xyz + (size_t)b * NN * 3;
    for (int m = threadIdx.x; m < NN; m += 256)
        pts[m] = make_float4(xb[m*3], xb[m*3+1], xb[m*3+2], 0.f);
    __syncthreads();

    int qloc = threadIdx.x & 63;
    int sub  = threadIdx.x >> 6;
    int qi   = chunk*64 + qloc;
    float4 qp = pts[qi];

    float bd[16]; int bi[16];
    #pragma unroll
    for (int i = 0; i < 16; i++) { bd[i] = 3.4e38f; bi[i] = 0; }

    int base = sub * 1024;
    #pragma unroll 2
    for (int m = base; m < base + 1024; m += 2) {
        float4 p0 = pts[m], p1 = pts[m+1];
        float dx0 = qp.x-p0.x, dy0 = qp.y-p0.y, dz0 = qp.z-p0.z;
        float dx1 = qp.x-p1.x, dy1 = qp.y-p1.y, dz1 = qp.z-p1.z;
        float d0 = fmaf(dx0,dx0, fmaf(dy0,dy0, dz0*dz0));
        float d1 = fmaf(dx1,dx1, fmaf(dy1,dy1, dz1*dz1));
        if (d0 < bd[15]) ins16(bd, bi, d0, m);
        if (d1 < bd[15]) ins16(bd, bi, d1, m+1);
    }

    if (sub) {
        #pragma unroll
        for (int i = 0; i < 16; i++) { md[qloc][sub-1][i] = bd[i]; mi[qloc][sub-1][i] = bi[i]; }
    }
    __syncthreads();
    if (sub == 0) {
        #pragma unroll
        for (int l = 0; l < 3; l++) {
            #pragma unroll
            for (int i = 0; i < 16; i++) {
                float d = md[qloc][l][i];
                if (d < bd[15]) ins16(bd, bi, d, mi[qloc][l][i]);
            }
        }
        #pragma unroll
        for (int i = 0; i < 16; i++)
            g_idx[(size_t)(b*NN + qi)*KK + i] = bi[i];
    }
}

// ---------------- shared MMA helpers ----------------
__device__ __forceinline__ void load_w512(uint32_t sB, const __half* __restrict__ W,
                                          int kt, int buf, int tid)
{
    uint32_t base = sB + (uint32_t)buf*BBYTES;
    #pragma unroll
    for (int i = 0; i < 4; i++) {
        int ch = tid + i*512;
        int r = ch >> 3, c = ch & 7;
        CP16(base + r*144 + c*16, W + (size_t)r*256 + kt*64 + c*8);
    }
}

__device__ __forceinline__ void load_wpost(uint32_t sB, int kt, int buf, int tid)
{
    uint32_t base = sB + (uint32_t)buf*BBYTES;
    int r = tid >> 3, c = tid & 7;
    CP16(base + r*144 + c*16, g_Wposth + (size_t)r*256 + kt*64 + c*8);
}

__device__ __forceinline__ void mma_tile128(uint32_t ab, uint32_t bb, float acc[4][4][4])
{
    #pragma unroll
    for (int ks = 0; ks < 4; ks++) {
        uint32_t bf[2][4];
        LDSM4(bf[0][0], bf[0][1], bf[0][2], bf[0][3], bb + ks*32);
        LDSM4(bf[1][0], bf[1][1], bf[1][2], bf[1][3], bb + 16*144 + ks*32);
        #pragma unroll
        for (int mt = 0; mt < 4; mt++) {
            uint32_t af[4];
            LDSM4(af[0], af[1], af[2], af[3], ab + mt*(16*APITCH_B) + ks*32);
            #pragma unroll
            for (int nt = 0; nt < 4; nt++)
                mma16816(acc[mt][nt], af,
                         bf[nt >> 1][(nt & 1)*2], bf[nt >> 1][(nt & 1)*2 + 1]);
        }
    }
}

__device__ __forceinline__ void zero_acc4(float acc[4][4][4])
{
    #pragma unroll
    for (int mt = 0; mt < 4; mt++)
        #pragma unroll
        for (int nt = 0; nt < 4; nt++)
            #pragma unroll
            for (int j = 0; j < 4; j++) acc[mt][nt][j] = 0.f;
}

__device__ __forceinline__ void ln_stats8(const float2* rowred, float inv, float& mu, float& rs)
{
    float S = 0.f, Q = 0.f;
    #pragma unroll
    for (int i = 0; i < 8; i++) { float2 e = rowred[i]; S += e.x; Q += e.y; }
    mu = S * inv;
    float var = Q * inv - mu*mu;
    rs = rsqrtf(var + 1e-5f);
}

// ---------------- qkvmma: 128 rows/CTA, fused LN, fp16 output ----------------
__global__ void __launch_bounds__(512) qkvmma_kernel(
    const float* __restrict__ features, const float* __restrict__ b_pre,
    const float* __restrict__ gdm, const float* __restrict__ bdm, int p0base)
{
    extern __shared__ char smemc[];
    __shared__ float2 red[128][8];
    uint32_t sA = smem_u32(smemc);
    uint32_t sB = sA + ABYTES128;
    const int tid = threadIdx.x, lane = tid & 31, w = tid >> 5;
    const int wn = w & 7, wm2 = w >> 3;
    const int p0 = p0base + blockIdx.x * 128;

    {
        #pragma unroll
        for (int i = 0; i < 4; i++) {
            int ch = tid + i*512; int r = ch >> 3, c = ch & 7;
            CP16(sB + r*144 + c*16, g_Wpreh + r*64 + c*8);
        }
        CP_COMMIT();
        load_w512(sB, g_WQh, 0, 1, tid); CP_COMMIT();
    }

    for (int ch = tid; ch < 128*32; ch += 512) {
        int r = ch >> 5, c2 = ch & 31;
        float2 v = *(const float2*)&features[(size_t)(p0 + r)*DP + c2*2];
        *(half2*)(smemc + (size_t)r*APITCH_B + c2*4) = __floats2half2_rn(v.x, v.y);
    }

    const uint32_t aBase = sA + (uint32_t)(wm2*64 + (lane & 15))*APITCH_B + (lane >> 4)*16;
    const uint32_t bAddr = sB + (uint32_t)(wn*32 + ((lane >> 4) & 1)*8 + (lane & 7))*144
                              + ((lane >> 3) & 1)*16;

    float acc[4][4][4];

    zero_acc4(acc);
    CP_WAIT1(); __syncthreads();
    mma_tile128(aBase, bAddr, acc);
    __syncthreads();
    load_w512(sB, g_WQh, 1, 0, tid); CP_COMMIT();
    {
        const int r0b = lane >> 2;
        #pragma unroll
        for (int mt = 0; mt < 4; mt++) {
            int gmt = wm2*4 + mt;
            int r0 = gmt*16 + r0b, r1 = r0 + 8;
            #pragma unroll
            for (int nt = 0; nt < 4; nt++) {
                int col = wn*32 + nt*8 + (lane & 3)*2;
                float b0 = b_pre[col], b1 = b_pre[col+1];
                *(half2*)(smemc + (size_t)r0*APITCH_B + col*2) =
                    __floats2half2_rn(acc[mt][nt][0] + b0, acc[mt][nt][1] + b1);
                *(half2*)(smemc + (size_t)r1*APITCH_B + col*2) =
                    __floats2half2_rn(acc[mt][nt][2] + b0, acc[mt][nt][3] + b1);
            }
        }
    }

    const __half* Ws[3] = { g_WQh, g_WKh, g_WVh };
    __half* outs[3] = { g_Qh, g_Kh, g_Vh };
    for (int s = 0; s < 3; s++) {
        zero_acc4(acc);
        for (int kt = 0; kt < 4; kt++) {
            int c = 1 + s*4 + kt;
            if (c == 12) { CP_WAIT0(); } else { CP_WAIT1(); }
            __syncthreads();
            mma_tile128(aBase + kt*128, bAddr + (uint32_t)(c & 1)*BBYTES, acc);
            __syncthreads();
            int nc = c + 2;
            if (nc <= 12) {
                int ns = (nc - 1) >> 2, nkt = (nc - 1) & 3;
                load_w512(sB, Ws[ns], nkt, nc & 1, tid);
                CP_COMMIT();
            }
        }
        {
            const int r0b = lane >> 2;
            #pragma unroll
            for (int mt = 0; mt < 4; mt++) {
                int gmt = wm2*4 + mt;
                int r0 = gmt*16 + r0b, r1 = r0 + 8;
                float s0=0.f, q0=0.f, s1=0.f, q1=0.f;
                #pragma unroll
                for (int nt = 0; nt < 4; nt++) {
                    float a0=acc[mt][nt][0], a1=acc[mt][nt][1];
                    float a2=acc[mt][nt][2], a3=acc[mt][nt][3];
                    s0 += a0+a1; q0 += a0*a0+a1*a1;
                    s1 += a2+a3; q1 += a2*a2+a3*a3;
                }
                #pragma unroll
                for (int o = 1; o < 4; o <<= 1) {
                    s0 += __shfl_xor_sync(~0u, s0, o); q0 += __shfl_xor_sync(~0u, q0, o);
                    s1 += __shfl_xor_sync(~0u, s1, o); q1 += __shfl_xor_sync(~0u, q1, o);
                }
                if ((lane & 3) == 0) {
                    red[r0][wn] = make_float2(s0, q0);
                    red[r1][wn] = make_float2(s1, q1);
                }
            }
        }
        __syncthreads();
        __half* outg = outs[s];
        {
            const int r0b = lane >> 2;
            #pragma unroll
            for (int mt = 0; mt < 4; mt++) {
                int gmt = wm2*4 + mt;
                int r0 = gmt*16 + r0b, r1 = r0 + 8;
                float mu0, rs0, mu1, rs1;
                ln_stats8(red[r0], 1.f/DM, mu0, rs0);
                ln_stats8(red[r1], 1.f/DM, mu1, rs1);
                #pragma unroll
                for (int nt = 0; nt < 4; nt++) {
                    int col = wn*32 + nt*8 + (lane & 3)*2;
                    float g0 = gdm[col], g1 = gdm[col+1];
                    float b0 = bdm[col], b1 = bdm[col+1];
                    *(half2*)&outg[(size_t)(p0+r0)*DM + col] = __floats2half2_rn(
                        (acc[mt][nt][0]-mu0)*rs0*g0 + b0, (acc[mt][nt][1]-mu0)*rs0*g1 + b1);
                    *(half2*)&outg[(size_t)(p0+r1)*DM + col] = __floats2half2_rn(
                        (acc[mt][nt][2]-mu1)*rs1*g0 + b0, (acc[mt][nt][3]-mu1)*rs1*g1 + b1);
                }
            }
        }
        __syncthreads();
    }
}

// ---------------- mega kernel (R13 config; fp16 res out) ----------------
__global__ void __launch_bounds__(512) mega_kernel(
    const float* __restrict__ xyz, const float* __restrict__ Wp1, int m0base)
{
    extern __shared__ char smemc[];
    uint32_t sA = smem_u32(smemc);
    uint32_t sB = sA + BOFF;

    const int tid  = threadIdx.x;
    const int lane = tid & 31, w = tid >> 5;
    const int wn = w & 7, wm2 = w >> 3;
    const int m0    = m0base + blockIdx.x * 128;
    const int pbase = m0 >> 4;
    const int bq    = pbase >> 12;

    __shared__ float rel3[128][3];
    __shared__ int   idxs[128];

    const __half* Ws[3] = { g_Wp2h, g_Wa1h, g_Wa2h };

    load_w512(sB, g_Wp2h, 0, 0, tid); CP_COMMIT();
    load_w512(sB, g_Wp2h, 1, 1, tid); CP_COMMIT();

    if (tid < 128) {
        int m  = m0 + tid;
        int pt = m >> 4;
        int n  = pt & (NN - 1);
        int id = g_idx[(size_t)pt*KK + (m & 15)];
        idxs[tid] = id;
        const float* xb = xyz + (size_t)bq*NN*3;
        rel3[tid][0] = xb[n*3 + 0] - xb[id*3 + 0];
        rel3[tid][1] = xb[n*3 + 1] - xb[id*3 + 1];
        rel3[tid][2] = xb[n*3 + 2] - xb[id*3 + 2];
    }
    __syncthreads();

    {
        int c0 = (tid & 127)*2;
        int j0 = (tid >> 7)*32;
        float a0 = Wp1[c0*3+0], a1 = Wp1[c0*3+1], a2 = Wp1[c0*3+2];
        float d0 = Wp1[c0*3+3], d1 = Wp1[c0*3+4], d2 = Wp1[c0*3+5];
        #pragma unroll 8
        for (int j = j0; j < j0 + 32; j++) {
            float h0 = fmaf(a0, rel3[j][0], fmaf(a1, rel3[j][1], a2*rel3[j][2]));
            float h1 = fmaf(d0, rel3[j][0], fmaf(d1, rel3[j][1], d2*rel3[j][2]));
            *(half2*)(smemc + (size_t)j*APITCH_B + c0*2) =
                __floats2half2_rn(fmaxf(h0, 0.f), fmaxf(h1, 0.f));
        }
    }

    const uint32_t aBase = sA + (uint32_t)(wm2*64 + (lane & 15))*APITCH_B + (lane >> 4)*16;
    const uint32_t bAddr = sB + (uint32_t)(wn*32 + ((lane >> 4) & 1)*8 + (lane & 7))*144
                              + ((lane >> 3) & 1)*16;

    float acc[4][4][4];

    #pragma unroll 1
    for (int c = 0; c < 12; c++) {
        const int kt = c & 3;
        if (kt == 0) zero_acc4(acc);

        if (c >= 10) { CP_WAIT0(); } else { CP_WAIT1(); }
        __syncthreads();

        mma_tile128(aBase + kt*128, bAddr + (uint32_t)(c & 1)*BBYTES, acc);
        __syncthreads();

        if (c + 2 < 12) {
            int nc = c + 2;
            load_w512(sB, Ws[nc >> 2], nc & 3, c & 1, tid);
            CP_COMMIT();
        }

        if (kt == 3) {
            const int stage = c >> 2;
            const int r0b  = lane >> 2;
            const int colb = wn*32 + (lane & 3)*2;

            if (stage == 0) {
                #pragma unroll
                for (int mt = 0; mt < 4; mt++) {
                    int gmt = wm2*4 + mt;
                    int pt  = pbase + gmt;
                    int r0  = gmt*16 + r0b, r1 = r0 + 8;
                    const __half* qp  = g_Qh + (size_t)pt*DM;
                    const __half* k0p = g_Kh + ((size_t)(bq << 12) + idxs[r0])*DM;
                    const __half* k1p = g_Kh + ((size_t)(bq << 12) + idxs[r1])*DM;
                    const __half* v0p = g_Vh + ((size_t)(bq << 12) + idxs[r0])*DM;
                    const __half* v1p = g_Vh + ((size_t)(bq << 12) + idxs[r1])*DM;
                    #pragma unroll
                    for (int nt = 0; nt < 4; nt++) {
                        int col = colb + nt*8;
                        float2 q  = __half22float2(*(const half2*)(qp  + col));
                        float2 ka = __half22float2(*(const half2*)(k0p + col));
                        float2 kb = __half22float2(*(const half2*)(k1p + col));
                        float2 va = __half22float2(*(const half2*)(v0p + col));
                        float2 vb = __half22float2(*(const half2*)(v1p + col));
                        float p00 = acc[mt][nt][0], p01 = acc[mt][nt][1];
                        float p10 = acc[mt][nt][2], p11 = acc[mt][nt][3];
                        *(half2*)(smemc + (size_t)r0*APITCH_B + col*2) =
                            __floats2half2_rn(q.x - ka.x + p00, q.y - ka.y + p01);
                        *(half2*)(smemc + (size_t)r1*APITCH_B + col*2) =
                            __floats2half2_rn(q.x - kb.x + p10, q.y - kb.y + p11);
                        *(half2*)(smemc + UOFF + (size_t)r0*APITCH_B + col*2) =
                            __floats2half2_rn(va.x + p00, va.y + p01);
                        *(half2*)(smemc + UOFF + (size_t)r1*APITCH_B + col*2) =
                            __floats2half2_rn(vb.x + p10, vb.y + p11);
                    }
                }
            } else if (stage == 1) {
                #pragma unroll
                for (int mt = 0; mt < 4; mt++) {
                    int gmt = wm2*4 + mt;
                    int r0  = gmt*16 + r0b, r1 = r0 + 8;
                    #pragma unroll
                    for (int nt = 0; nt < 4; nt++) {
                        int col = colb + nt*8;
                        *(half2*)(smemc + (size_t)r0*APITCH_B + col*2) =
                            __floats2half2_rn(fmaxf(acc[mt][nt][0], 0.f), fmaxf(acc[mt][nt][1], 0.f));
                        *(half2*)(smemc + (size_t)r1*APITCH_B + col*2) =
                            __floats2half2_rn(fmaxf(acc[mt][nt][2], 0.f), fmaxf(acc[mt][nt][3], 0.f));
                    }
                }
            } else {
                const float sc = 0.0625f;
                #pragma unroll
                for (int mt = 0; mt < 4; mt++) {
                    int gmt = wm2*4 + mt;
                    int pt  = pbase + gmt;
                    int r0  = gmt*16 + r0b, r1 = r0 + 8;
                    #pragma unroll
                    for (int nt = 0; nt < 4; nt++) {
                        int col = colb + nt*8;
                        float2 ua = __half22float2(
                            *(half2*)(smemc + UOFF + (size_t)r0*APITCH_B + col*2));
                        float2 ub = __half22float2(
                            *(half2*)(smemc + UOFF + (size_t)r1*APITCH_B + col*2));
                        float rout[2];
                        #pragma unroll
                        for (int p = 0; p < 2; p++) {
                            float x0 = acc[mt][nt][p]     * sc;
                            float x1 = acc[mt][nt][2 + p] * sc;
                            float mx = fmaxf(x0, x1);
                            #pragma unroll
                            for (int o = 4; o < 32; o <<= 1)
                                mx = fmaxf(mx, __shfl_xor_sync(0xffffffffu, mx, o));
                            float e0 = __expf(x0 - mx), e1 = __expf(x1 - mx);
                            float s  = e0 + e1;
                            float uu0 = p ? ua.y : ua.x;
                            float uu1 = p ? ub.y : ub.x;
                            float ww = e0*uu0 + e1*uu1;
                            #pragma unroll
                            for (int o = 4; o < 32; o <<= 1) {
                                s  += __shfl_xor_sync(0xffffffffu, s , o);
                                ww += __shfl_xor_sync(0xffffffffu, ww, o);
                            }
                            rout[p] = ww / s;
                        }
                        if (lane < 4)
                            *(half2*)&g_resh[(size_t)pt*DM + col] =
                                __floats2half2_rn(rout[0], rout[1]);
                    }
                }
            }
        }
    }
}

// ---------------- finalmma: 128 rows, cp.async A, proj+LN+post+LN+residual ----
__global__ void __launch_bounds__(512) finalmma_kernel(
    const float* __restrict__ features, const float* __restrict__ b_post,
    const float* __restrict__ gdm, const float* __restrict__ bdm,
    const float* __restrict__ gdp, const float* __restrict__ bdp,
    float* __restrict__ out, int p0base)
{
    extern __shared__ char smemc[];
    __shared__ float2 red[128][8];
    uint32_t sA = smem_u32(smemc);
    uint32_t sB = sA + ABYTES128;
    const int tid = threadIdx.x, lane = tid & 31, w = tid >> 5;
    const int wn = w & 7, wm2 = w >> 3;
    const int p0 = p0base + blockIdx.x * 128;

    // group 0: Wproj chunk0 + A tile (g_resh, fp16, direct cp.async)
    load_w512(sB, g_Wprojh, 0, 0, tid);
    #pragma unroll
    for (int i = 0; i < 8; i++) {
        int ch = tid + i*512;
        int r = ch >> 5, c = ch & 31;
        CP16(sA + (uint32_t)r*APITCH_B + c*16, g_resh + (size_t)(p0 + r)*DM + c*8);
    }
    CP_COMMIT();
    load_w512(sB, g_Wprojh, 1, 1, tid); CP_COMMIT();

    const uint32_t aBase = sA + (uint32_t)(wm2*64 + (lane & 15))*APITCH_B + (lane >> 4)*16;
    const uint32_t bAddr = sB + (uint32_t)(wn*32 + ((lane >> 4) & 1)*8 + (lane & 7))*144
                              + ((lane >> 3) & 1)*16;
    const uint32_t bAddrP = sB + (uint32_t)(wn*8 + (lane & 7))*144 + (lane >> 3)*16;

    float acc[4][4][4];
    zero_acc4(acc);
    for (int kt = 0; kt < 4; kt++) {
        CP_WAIT1();
        __syncthreads();
        mma_tile128(aBase + kt*128, bAddr + (uint32_t)(kt & 1)*BBYTES, acc);
        __syncthreads();
        int nc = kt + 2;
        if (nc < 4) load_w512(sB, g_Wprojh, nc, kt & 1, tid);
        else        load_wpost(sB, nc - 4, kt & 1, tid);
        CP_COMMIT();
    }

    // LN(256) -> z fp16 back into A
    {
        const int r0b = lane >> 2;
        #pragma unroll
        for (int mt = 0; mt < 4; mt++) {
            int gmt = wm2*4 + mt;
            int r0 = gmt*16 + r0b, r1 = r0 + 8;
            float s0=0.f, q0=0.f, s1=0.f, q1=0.f;
            #pragma unroll
            for (int nt = 0; nt < 4; nt++) {
                float a0=acc[mt][nt][0], a1=acc[mt][nt][1];
                float a2=acc[mt][nt][2], a3=acc[mt][nt][3];
                s0 += a0+a1; q0 += a0*a0+a1*a1;
                s1 += a2+a3; q1 += a2*a2+a3*a3;
            }
            #pragma unroll
            for (int o = 1; o < 4; o <<= 1) {
                s0 += __shfl_xor_sync(~0u, s0, o); q0 += __shfl_xor_sync(~0u, q0, o);
                s1 += __shfl_xor_sync(~0u, s1, o); q1 += __shfl_xor_sync(~0u, q1, o);
            }
            if ((lane & 3) == 0) {
                red[r0][wn] = make_float2(s0, q0);
                red[r1][wn] = make_float2(s1, q1);
            }
        }
        __syncthreads();
        #pragma unroll
        for (int mt = 0; mt < 4; mt++) {
            int gmt = wm2*4 + mt;
            int r0 = gmt*16 + r0b, r1 = r0 + 8;
            float mu0, rs0, mu1, rs1;
            ln_stats8(red[r0], 1.f/DM, mu0, rs0);
            ln_stats8(red[r1], 1.f/DM, mu1, rs1);
            #pragma unroll
            for (int nt = 0; nt < 4; nt++) {
                int col = wn*32 + nt*8 + (lane & 3)*2;
                float g0 = gdm[col], g1 = gdm[col+1];
                float b0 = bdm[col], b1 = bdm[col+1];
                *(half2*)(smemc + (size_t)r0*APITCH_B + col*2) = __floats2half2_rn(
                    (acc[mt][nt][0]-mu0)*rs0*g0 + b0, (acc[mt][nt][1]-mu0)*rs0*g1 + b1);
                *(half2*)(smemc + (size_t)r1*APITCH_B + col*2) = __floats2half2_rn(
                    (acc[mt][nt][2]-mu1)*rs1*g0 + b0, (acc[mt][nt][3]-mu1)*rs1*g1 + b1);
            }
        }
    }

    // post GEMM via HMMA: chunks 4..7, N=64
    float accp[4][4];
    #pragma unroll
    for (int mt = 0; mt < 4; mt++)
        #pragma unroll
        for (int j = 0; j < 4; j++) accp[mt][j] = 0.f;

    for (int kt = 0; kt < 4; kt++) {
        int c = 4 + kt;
        if (c == 7) { CP_WAIT0(); } else { CP_WAIT1(); }
        __syncthreads();

        uint32_t ab = aBase + kt*128;
        uint32_t bb = bAddrP + (uint32_t)(c & 1)*BBYTES;
        #pragma unroll
        for (int ks2 = 0; ks2 < 2; ks2++) {
            uint32_t bfp[4];
            LDSM4(bfp[0], bfp[1], bfp[2], bfp[3], bb + ks2*64);
            #pragma unroll
            for (int sub = 0; sub < 2; sub++) {
                int ks = ks2*2 + sub;
                #pragma unroll
                for (int mt = 0; mt < 4; mt++) {
                    uint32_t af[4];
                    LDSM4(af[0], af[1], af[2], af[3], ab + mt*(16*APITCH_B) + ks*32);
                    mma16816(accp[mt], af, bfp[sub*2], bfp[sub*2 + 1]);
                }
            }
        }
        __syncthreads();
        if (kt + 2 < 4) { load_wpost(sB, kt + 2, c & 1, tid); CP_COMMIT(); }
    }

    // + b_post, LN(64), + residual
    {
        const int r0b = lane >> 2;
        const int col = wn*8 + (lane & 3)*2;
        float b0 = b_post[col], b1 = b_post[col+1];
        #pragma unroll
        for (int mt = 0; mt < 4; mt++) {
            accp[mt][0] += b0; accp[mt][1] += b1;
            accp[mt][2] += b0; accp[mt][3] += b1;
        }
        #pragma unroll
        for (int mt = 0; mt < 4; mt++) {
            int gmt = wm2*4 + mt;
            int r0 = gmt*16 + r0b, r1 = r0 + 8;
            float s0 = accp[mt][0] + accp[mt][1];
            float q0 = accp[mt][0]*accp[mt][0] + accp[mt][1]*accp[mt][1];
            float s1 = accp[mt][2] + accp[mt][3];
            float q1 = accp[mt][2]*accp[mt][2] + accp[mt][3]*accp[mt][3];
            #pragma unroll
            for (int o = 1; o < 4; o <<= 1) {
                s0 += __shfl_xor_sync(~0u, s0, o); q0 += __shfl_xor_sync(~0u, q0, o);
                s1 += __shfl_xor_sync(~0u, s1, o); q1 += __shfl_xor_sync(~0u, q1, o);
            }
            if ((lane & 3) == 0) {
                red[r0][wn] = make_float2(s0, q0);
                red[r1][wn] = make_float2(s1, q1);
            }
        }
        __syncthreads();

        float g0 = gdp[col], g1 = gdp[col+1];
        float bb0 = bdp[col], bb1 = bdp[col+1];
        #pragma unroll
        for (int mt = 0; mt < 4; mt++) {
            int gmt = wm2*4 + mt;
            int r0 = gmt*16 + r0b, r1 = r0 + 8;
            float mu0, rs0, mu1, rs1;
            ln_stats8(red[r0], 1.f/DP, mu0, rs0);
            ln_stats8(red[r1], 1.f/DP, mu1, rs1);
            size_t base0 = (size_t)(p0 + r0)*DP + col;
            size_t base1 = (size_t)(p0 + r1)*DP + col;
            float2 f0 = *(const float2*)&features[base0];
            float2 f1 = *(const float2*)&features[base1];
            *(float2*)&out[base0] = make_float2(
                (accp[mt][0]-mu0)*rs0*g0 + bb0 + f0.x,
                (accp[mt][1]-mu0)*rs0*g1 + bb1 + f0.y);
            *(float2*)&out[base1] = make_float2(
                (accp[mt][2]-mu1)*rs1*g0 + bb0 + f1.x,
                (accp[mt][3]-mu1)*rs1*g1 + bb1 + f1.y);
        }
    }
}

// ---------------- launch: batch-split dual-stream pipeline ----------------
extern "C" void kernel_launch(void* const* d_in, const int* in_sizes, int n_in,
                              void* d_out, int out_size)
{
    const float* xyz      = (const float*)d_in[0];
    const float* features = (const float*)d_in[1];
    const float* W_pre    = (const float*)d_in[2];
    const float* b_pre    = (const float*)d_in[3];
    const float* W_post   = (const float*)d_in[4];
    const float* b_post   = (const float*)d_in[5];
    const float* Wp1      = (const float*)d_in[6];
    const float* Wp2      = (const float*)d_in[7];
    const float* Wa1      = (const float*)d_in[8];
    const float* Wa2      = (const float*)d_in[9];
    const float* WQ       = (const float*)d_in[10];
    const float* WK       = (const float*)d_in[11];
    const float* WV       = (const float*)d_in[12];
    const float* Wproj    = (const float*)d_in[13];
    const float* g_dm     = (const float*)d_in[14];
    const float* b_dm     = (const float*)d_in[15];
    const float* g_dp     = (const float*)d_in[16];
    const float* b_dp     = (const float*)d_in[17];
    float* out = (float*)d_out;

    static cudaStream_t sB = nullptr, sK = nullptr;
    static cudaEvent_t evF, evP, evKA, evKB, evB;
    if (!sB) {
        cudaStreamCreateWithFlags(&sB, cudaStreamNonBlocking);
        cudaStreamCreateWithFlags(&sK, cudaStreamNonBlocking);
        cudaEventCreateWithFlags(&evF,  cudaEventDisableTiming);
        cudaEventCreateWithFlags(&evP,  cudaEventDisableTiming);
        cudaEventCreateWithFlags(&evKA, cudaEventDisableTiming);
        cudaEventCreateWithFlags(&evKB, cudaEventDisableTiming);
        cudaEventCreateWithFlags(&evB,  cudaEventDisableTiming);
        cudaFuncSetAttribute(knn_kernel, cudaFuncAttributeMaxDynamicSharedMemorySize,
                             NN * (int)sizeof(float4));
        cudaFuncSetAttribute(mega_kernel,     cudaFuncAttributeMaxDynamicSharedMemorySize, MEGA_SMEM);
        cudaFuncSetAttribute(qkvmma_kernel,   cudaFuncAttributeMaxDynamicSharedMemorySize, QKV_SMEM);
        cudaFuncSetAttribute(finalmma_kernel, cudaFuncAttributeMaxDynamicSharedMemorySize, QKV_SMEM);
    }

    // fork knn (independent of prep)
    cudaEventRecord(evF, 0);
    cudaStreamWaitEvent(sK, evF, 0);
    knn_kernel<<<128, 256, NN*sizeof(float4), sK>>>(xyz, 0);   // batches 0,1
    cudaEventRecord(evKA, sK);
    knn_kernel<<<128, 256, NN*sizeof(float4), sK>>>(xyz, 2);   // batches 2,3
    cudaEventRecord(evKB, sK);

    // prep on main, then fork half-B
    prep_kernel<<<256, 256>>>(W_pre, WQ, WK, WV, Wproj, W_post, Wp2, Wa1, Wa2);
    cudaEventRecord(evP, 0);
    cudaStreamWaitEvent(sB, evP, 0);

    // half A (batches 0,1) on main stream
    qkvmma_kernel<<<NPTS/256, 512, QKV_SMEM>>>(features, b_pre, g_dm, b_dm, 0);
    cudaStreamWaitEvent(0, evKA, 0);
    mega_kernel<<<MTOT/256, 512, MEGA_SMEM>>>(xyz, Wp1, 0);
    finalmma_kernel<<<NPTS/256, 512, QKV_SMEM>>>(features, b_post, g_dm, b_dm,
                                                 g_dp, b_dp, out, 0);

    // half B (batches 2,3) on sB
    qkvmma_kernel<<<NPTS/256, 512, QKV_SMEM, sB>>>(features, b_pre, g_dm, b_dm, NPTS/2);
    cudaStreamWaitEvent(sB, evKB, 0);
    mega_kernel<<<MTOT/256, 512, MEGA_SMEM, sB>>>(xyz, Wp1, MTOT/2);
    finalmma_kernel<<<NPTS/256, 512, QKV_SMEM, sB>>>(features, b_post, g_dm, b_dm,
                                                     g_dp, b_dp, out, NPTS/2);
    cudaEventRecord(evB, sB);

    // rejoin
    cudaStreamWaitEvent(0, evB, 0);
}

// round 16
// speedup vs baseline: 1.0272x; 1.0272x over previous
#include <cuda_runtime.h>
#include <cuda_fp16.h>
#include <cstddef>
#include <cstdint>

#define BB 4
#define NN 4096
#define KK 16
#define DP 64
#define DM 256
#define NPTS (BB*NN)
#define MTOT (NPTS*KK)

// ---------------- device-global scratch (no allocs allowed) ----------------
__device__ __half g_Wposth[DP*DM];   // [n=64][k=256]
__device__ __half g_Wpreh[DM*DP];    // [n=256][k=64]
__device__ __half g_WQh [DM*DM];     // [n][k]
__device__ __half g_WKh [DM*DM];
__device__ __half g_WVh [DM*DM];
__device__ __half g_Wprojh[DM*DM];
__device__ __half g_Wp2h[DM*DM];
__device__ __half g_Wa1h[DM*DM];
__device__ __half g_Wa2h[DM*DM];
__device__ __half g_Qh [NPTS*DM];
__device__ __half g_Kh [NPTS*DM];
__device__ __half g_Vh [NPTS*DM];
__device__ int   g_idx[NPTS*KK];
__device__ __half g_resh[(size_t)NPTS*DM];

// ---------------- helpers ----------------
__device__ __forceinline__ uint32_t smem_u32(const void* p) {
    uint32_t a;
    asm("{ .reg .u64 t; cvta.to.shared.u64 t, %1; cvt.u32.u64 %0, t; }" : "=r"(a) : "l"(p));
    return a;
}
#define CP16(dst, src) asm volatile("cp.async.cg.shared.global [%0], [%1], 16;" :: "r"(dst), "l"(src) : "memory")
#define CP_COMMIT()    asm volatile("cp.async.commit_group;" ::: "memory")
#define CP_WAIT1()     asm volatile("cp.async.wait_group 1;" ::: "memory")
#define CP_WAIT0()     asm volatile("cp.async.wait_group 0;" ::: "memory")
#define LDSM4(r0,r1,r2,r3,a) \
    asm volatile("ldmatrix.sync.aligned.m8n8.x4.shared.b16 {%0,%1,%2,%3}, [%4];" \
                 : "=r"(r0),"=r"(r1),"=r"(r2),"=r"(r3) : "r"(a))

__device__ __forceinline__ void mma16816(float* c, const uint32_t* a, uint32_t b0, uint32_t b1) {
    asm volatile("mma.sync.aligned.m16n8k16.row.col.f32.f16.f16.f32 "
        "{%0,%1,%2,%3}, {%4,%5,%6,%7}, {%8,%9}, {%0,%1,%2,%3};"
        : "+f"(c[0]), "+f"(c[1]), "+f"(c[2]), "+f"(c[3])
        : "r"(a[0]), "r"(a[1]), "r"(a[2]), "r"(a[3]), "r"(b0), "r"(b1));
}

#define APITCH_B 528
#define ABYTES128 (128*APITCH_B)           // 67584
#define BBYTES    (256*144)                // 36864
#define QKV_SMEM  (ABYTES128 + 2*BBYTES)   // 141312
#define UOFF      ABYTES128
#define BOFF      (2*ABYTES128)
#define MEGA_SMEM (2*ABYTES128 + 2*BBYTES) // 208896

// ---------------- weight prep (split) ----------------
__global__ void prepA_kernel(const float* __restrict__ W_pre,
                             const float* __restrict__ WQ, const float* __restrict__ WK,
                             const float* __restrict__ WV, const float* __restrict__ b_unused)
{
    int t = blockIdx.x * blockDim.x + threadIdx.x;
    if (t < DM*DP) g_Wpreh[t] = __float2half_rn(W_pre[t]);
    if (t < DM*DM) {
        g_WQh[t] = __float2half_rn(WQ[t]);
        g_WKh[t] = __float2half_rn(WK[t]);
        g_WVh[t] = __float2half_rn(WV[t]);
    }
}

__global__ void prepB_kernel(const float* __restrict__ Wproj, const float* __restrict__ W_post,
                             const float* __restrict__ Wp2,   const float* __restrict__ Wa1,
                             const float* __restrict__ Wa2)
{
    int t = blockIdx.x * blockDim.x + threadIdx.x;
    if (t < DM*DP) g_Wposth[t] = __float2half_rn(W_post[t]);
    if (t < DM*DM) {
        g_Wprojh[t] = __float2half_rn(Wproj[t]);
        g_Wp2h[t] = __float2half_rn(Wp2[t]);
        g_Wa1h[t] = __float2half_rn(Wa1[t]);
        g_Wa2h[t] = __float2half_rn(Wa2[t]);
    }
}

// ---------------- kNN v3 (unchanged) ----------------
__device__ __forceinline__ void ins16(float* bd, int* bi, float d, int m)
{
    #pragma unroll
    for (int i = 15; i >= 1; i--) {
        bool c1 = d < bd[i-1];
        bool c2 = d < bd[i];
        float nb = c1 ? bd[i-1] : (c2 ? d : bd[i]);
        int   ni = c1 ? bi[i-1] : (c2 ? m : bi[i]);
        bd[i] = nb; bi[i] = ni;
    }
    if (d < bd[0]) { bi[0] = m; bd[0] = d; }
}

__global__ void __launch_bounds__(256) knn_kernel(const float* __restrict__ xyz)
{
    extern __shared__ float4 pts[];
    __shared__ float md[64][3][16];
    __shared__ int   mi[64][3][16];

    int b     = blockIdx.x >> 6;
    int chunk = blockIdx.x & 63;
    const float* xb = xyz + (size_t)b * NN * 3;
    for (int m = threadIdx.x; m < NN; m += 256)
        pts[m] = make_float4(xb[m*3], xb[m*3+1], xb[m*3+2], 0.f);
    __syncthreads();

    int qloc = threadIdx.x & 63;
    int sub  = threadIdx.x >> 6;
    int qi   = chunk*64 + qloc;
    float4 qp = pts[qi];

    float bd[16]; int bi[16];
    #pragma unroll
    for (int i = 0; i < 16; i++) { bd[i] = 3.4e38f; bi[i] = 0; }

    int base = sub * 1024;
    #pragma unroll 2
    for (int m = base; m < base + 1024; m += 2) {
        float4 p0 = pts[m], p1 = pts[m+1];
        float dx0 = qp.x-p0.x, dy0 = qp.y-p0.y, dz0 = qp.z-p0.z;
        float dx1 = qp.x-p1.x, dy1 = qp.y-p1.y, dz1 = qp.z-p1.z;
        float d0 = fmaf(dx0,dx0, fmaf(dy0,dy0, dz0*dz0));
        float d1 = fmaf(dx1,dx1, fmaf(dy1,dy1, dz1*dz1));
        if (d0 < bd[15]) ins16(bd, bi, d0, m);
        if (d1 < bd[15]) ins16(bd, bi, d1, m+1);
    }

    if (sub) {
        #pragma unroll
        for (int i = 0; i < 16; i++) { md[qloc][sub-1][i] = bd[i]; mi[qloc][sub-1][i] = bi[i]; }
    }
    __syncthreads();
    if (sub == 0) {
        #pragma unroll
        for (int l = 0; l < 3; l++) {
            #pragma unroll
            for (int i = 0; i < 16; i++) {
                float d = md[qloc][l][i];
                if (d < bd[15]) ins16(bd, bi, d, mi[qloc][l][i]);
            }
        }
        #pragma unroll
        for (int i = 0; i < 16; i++)
            g_idx[(size_t)(b*NN + qi)*KK + i] = bi[i];
    }
}

// ---------------- shared MMA helpers ----------------
__device__ __forceinline__ void load_w512(uint32_t sB, const __half* __restrict__ W,
                                          int kt, int buf, int tid)
{
    uint32_t base = sB + (uint32_t)buf*BBYTES;
    #pragma unroll
    for (int i = 0; i < 4; i++) {
        int ch = tid + i*512;
        int r = ch >> 3, c = ch & 7;
        CP16(base + r*144 + c*16, W + (size_t)r*256 + kt*64 + c*8);
    }
}

__device__ __forceinline__ void load_wpost(uint32_t sB, int kt, int buf, int tid)
{
    uint32_t base = sB + (uint32_t)buf*BBYTES;
    int r = tid >> 3, c = tid & 7;
    CP16(base + r*144 + c*16, g_Wposth + (size_t)r*256 + kt*64 + c*8);
}

// 128-row tile, B-fragment software pipelined across ks
__device__ __forceinline__ void mma_tile128(uint32_t ab, uint32_t bb, float acc[4][4][4])
{
    uint32_t bf[2][2][4];
    LDSM4(bf[0][0][0], bf[0][0][1], bf[0][0][2], bf[0][0][3], bb);
    LDSM4(bf[0][1][0], bf[0][1][1], bf[0][1][2], bf[0][1][3], bb + 16*144);
    #pragma unroll
    for (int ks = 0; ks < 4; ks++) {
        int cur = ks & 1;
        if (ks < 3) {
            int nxt = cur ^ 1;
            LDSM4(bf[nxt][0][0], bf[nxt][0][1], bf[nxt][0][2], bf[nxt][0][3],
                  bb + (ks + 1)*32);
            LDSM4(bf[nxt][1][0], bf[nxt][1][1], bf[nxt][1][2], bf[nxt][1][3],
                  bb + 16*144 + (ks + 1)*32);
        }
        #pragma unroll
        for (int mt = 0; mt < 4; mt++) {
            uint32_t af[4];
            LDSM4(af[0], af[1], af[2], af[3], ab + mt*(16*APITCH_B) + ks*32);
            #pragma unroll
            for (int nt = 0; nt < 4; nt++)
                mma16816(acc[mt][nt], af,
                         bf[cur][nt >> 1][(nt & 1)*2], bf[cur][nt >> 1][(nt & 1)*2 + 1]);
        }
    }
}

__device__ __forceinline__ void zero_acc4(float acc[4][4][4])
{
    #pragma unroll
    for (int mt = 0; mt < 4; mt++)
        #pragma unroll
        for (int nt = 0; nt < 4; nt++)
            #pragma unroll
            for (int j = 0; j < 4; j++) acc[mt][nt][j] = 0.f;
}

__device__ __forceinline__ void ln_stats8(const float2* rowred, float inv, float& mu, float& rs)
{
    float S = 0.f, Q = 0.f;
    #pragma unroll
    for (int i = 0; i < 8; i++) { float2 e = rowred[i]; S += e.x; Q += e.y; }
    mu = S * inv;
    float var = Q * inv - mu*mu;
    rs = rsqrtf(var + 1e-5f);
}

// ---------------- qkvmma: 128 rows/CTA, fused LN, fp16 output ----------------
__global__ void __launch_bounds__(512) qkvmma_kernel(
    const float* __restrict__ features, const float* __restrict__ b_pre,
    const float* __restrict__ gdm, const float* __restrict__ bdm)
{
    extern __shared__ char smemc[];
    __shared__ float2 red[128][8];
    uint32_t sA = smem_u32(smemc);
    uint32_t sB = sA + ABYTES128;
    const int tid = threadIdx.x, lane = tid & 31, w = tid >> 5;
    const int wn = w & 7, wm2 = w >> 3;
    const int p0 = blockIdx.x * 128;

    {
        #pragma unroll
        for (int i = 0; i < 4; i++) {
            int ch = tid + i*512; int r = ch >> 3, c = ch & 7;
            CP16(sB + r*144 + c*16, g_Wpreh + r*64 + c*8);
        }
        CP_COMMIT();
        load_w512(sB, g_WQh, 0, 1, tid); CP_COMMIT();
    }

    for (int ch = tid; ch < 128*32; ch += 512) {
        int r = ch >> 5, c2 = ch & 31;
        float2 v = *(const float2*)&features[(size_t)(p0 + r)*DP + c2*2];
        *(half2*)(smemc + (size_t)r*APITCH_B + c2*4) = __floats2half2_rn(v.x, v.y);
    }

    const uint32_t aBase = sA + (uint32_t)(wm2*64 + (lane & 15))*APITCH_B + (lane >> 4)*16;
    const uint32_t bAddr = sB + (uint32_t)(wn*32 + ((lane >> 4) & 1)*8 + (lane & 7))*144
                              + ((lane >> 3) & 1)*16;

    float acc[4][4][4];

    zero_acc4(acc);
    CP_WAIT1(); __syncthreads();
    mma_tile128(aBase, bAddr, acc);
    __syncthreads();
    load_w512(sB, g_WQh, 1, 0, tid); CP_COMMIT();
    {
        const int r0b = lane >> 2;
        #pragma unroll
        for (int mt = 0; mt < 4; mt++) {
            int gmt = wm2*4 + mt;
            int r0 = gmt*16 + r0b, r1 = r0 + 8;
            #pragma unroll
            for (int nt = 0; nt < 4; nt++) {
                int col = wn*32 + nt*8 + (lane & 3)*2;
                float b0 = b_pre[col], b1 = b_pre[col+1];
                *(half2*)(smemc + (size_t)r0*APITCH_B + col*2) =
                    __floats2half2_rn(acc[mt][nt][0] + b0, acc[mt][nt][1] + b1);
                *(half2*)(smemc + (size_t)r1*APITCH_B + col*2) =
                    __floats2half2_rn(acc[mt][nt][2] + b0, acc[mt][nt][3] + b1);
            }
        }
    }

    const __half* Ws[3] = { g_WQh, g_WKh, g_WVh };
    __half* outs[3] = { g_Qh, g_Kh, g_Vh };
    for (int s = 0; s < 3; s++) {
        zero_acc4(acc);
        for (int kt = 0; kt < 4; kt++) {
            int c = 1 + s*4 + kt;
            if (c == 12) { CP_WAIT0(); } else { CP_WAIT1(); }
            __syncthreads();
            mma_tile128(aBase + kt*128, bAddr + (uint32_t)(c & 1)*BBYTES, acc);
            __syncthreads();
            int nc = c + 2;
            if (nc <= 12) {
                int ns = (nc - 1) >> 2, nkt = (nc - 1) & 3;
                load_w512(sB, Ws[ns], nkt, nc & 1, tid);
                CP_COMMIT();
            }
        }
        {
            const int r0b = lane >> 2;
            #pragma unroll
            for (int mt = 0; mt < 4; mt++) {
                int gmt = wm2*4 + mt;
                int r0 = gmt*16 + r0b, r1 = r0 + 8;
                float s0=0.f, q0=0.f, s1=0.f, q1=0.f;
                #pragma unroll
                for (int nt = 0; nt < 4; nt++) {
                    float a0=acc[mt][nt][0], a1=acc[mt][nt][1];
                    float a2=acc[mt][nt][2], a3=acc[mt][nt][3];
                    s0 += a0+a1; q0 += a0*a0+a1*a1;
                    s1 += a2+a3; q1 += a2*a2+a3*a3;
                }
                #pragma unroll
                for (int o = 1; o < 4; o <<= 1) {
                    s0 += __shfl_xor_sync(~0u, s0, o); q0 += __shfl_xor_sync(~0u, q0, o);
                    s1 += __shfl_xor_sync(~0u, s1, o); q1 += __shfl_xor_sync(~0u, q1, o);
                }
                if ((lane & 3) == 0) {
                    red[r0][wn] = make_float2(s0, q0);
                    red[r1][wn] = make_float2(s1, q1);
                }
            }
        }
        __syncthreads();
        __half* outg = outs[s];
        {
            const int r0b = lane >> 2;
            #pragma unroll
            for (int mt = 0; mt < 4; mt++) {
                int gmt = wm2*4 + mt;
                int r0 = gmt*16 + r0b, r1 = r0 + 8;
                float mu0, rs0, mu1, rs1;
                ln_stats8(red[r0], 1.f/DM, mu0, rs0);
                ln_stats8(red[r1], 1.f/DM, mu1, rs1);
                #pragma unroll
                for (int nt = 0; nt < 4; nt++) {
                    int col = wn*32 + nt*8 + (lane & 3)*2;
                    float g0 = gdm[col], g1 = gdm[col+1];
                    float b0 = bdm[col], b1 = bdm[col+1];
                    *(half2*)&outg[(size_t)(p0+r0)*DM + col] = __floats2half2_rn(
                        (acc[mt][nt][0]-mu0)*rs0*g0 + b0, (acc[mt][nt][1]-mu0)*rs0*g1 + b1);
                    *(half2*)&outg[(size_t)(p0+r1)*DM + col] = __floats2half2_rn(
                        (acc[mt][nt][2]-mu1)*rs1*g0 + b0, (acc[mt][nt][3]-mu1)*rs1*g1 + b1);
                }
            }
        }
        __syncthreads();
    }
}

// ---------------- mega kernel (V prefetched via cp.async into U region) -------
__global__ void __launch_bounds__(512) mega_kernel(
    const float* __restrict__ xyz, const float* __restrict__ Wp1)
{
    extern __shared__ char smemc[];
    uint32_t sA = smem_u32(smemc);
    uint32_t sB = sA + BOFF;

    const int tid  = threadIdx.x;
    const int lane = tid & 31, w = tid >> 5;
    const int wn = w & 7, wm2 = w >> 3;
    const int m0    = blockIdx.x * 128;
    const int pbase = m0 >> 4;
    const int bq    = pbase >> 12;

    __shared__ float rel3[128][3];
    __shared__ int   idxs[128];

    const __half* Ws[3] = { g_Wp2h, g_Wa1h, g_Wa2h };

    // group 0: weight chunk 0
    load_w512(sB, g_Wp2h, 0, 0, tid); CP_COMMIT();

    // prologue: neighbor ids + rel
    if (tid < 128) {
        int m  = m0 + tid;
        int pt = m >> 4;
        int n  = pt & (NN - 1);
        int id = g_idx[(size_t)pt*KK + (m & 15)];
        idxs[tid] = id;
        const float* xb = xyz + (size_t)bq*NN*3;
        rel3[tid][0] = xb[n*3 + 0] - xb[id*3 + 0];
        rel3[tid][1] = xb[n*3 + 1] - xb[id*3 + 1];
        rel3[tid][2] = xb[n*3 + 2] - xb[id*3 + 2];
    }
    __syncthreads();     // idxs visible

    // group 1: weight chunk 1 + gathered V rows into U region (overlaps stage-1 GEMM)
    load_w512(sB, g_Wp2h, 1, 1, tid);
    #pragma unroll
    for (int i = 0; i < 8; i++) {
        int ch = tid + i*512;              // 4096 chunks of 16 B = 128 rows x 512 B
        int r = ch >> 5, c = ch & 31;
        const __half* vp = g_Vh + ((size_t)(bq << 12) + idxs[r])*DM + c*8;
        CP16(sA + UOFF + (uint32_t)r*APITCH_B + c*16, vp);
    }
    CP_COMMIT();

    // h1 = relu(rel @ Wp1^T) -> A fp16
    {
        int c0 = (tid & 127)*2;
        int j0 = (tid >> 7)*32;
        float a0 = Wp1[c0*3+0], a1 = Wp1[c0*3+1], a2 = Wp1[c0*3+2];
        float d0 = Wp1[c0*3+3], d1 = Wp1[c0*3+4], d2 = Wp1[c0*3+5];
        #pragma unroll 8
        for (int j = j0; j < j0 + 32; j++) {
            float h0 = fmaf(a0, rel3[j][0], fmaf(a1, rel3[j][1], a2*rel3[j][2]));
            float h1 = fmaf(d0, rel3[j][0], fmaf(d1, rel3[j][1], d2*rel3[j][2]));
            *(half2*)(smemc + (size_t)j*APITCH_B + c0*2) =
                __floats2half2_rn(fmaxf(h0, 0.f), fmaxf(h1, 0.f));
        }
    }

    const uint32_t aBase = sA + (uint32_t)(wm2*64 + (lane & 15))*APITCH_B + (lane >> 4)*16;
    const uint32_t bAddr = sB + (uint32_t)(wn*32 + ((lane >> 4) & 1)*8 + (lane & 7))*144
                              + ((lane >> 3) & 1)*16;

    float acc[4][4][4];

    #pragma unroll 1
    for (int c = 0; c < 12; c++) {
        const int kt = c & 3;
        if (kt == 0) zero_acc4(acc);

        if (c >= 10) { CP_WAIT0(); } else { CP_WAIT1(); }
        __syncthreads();

        mma_tile128(aBase + kt*128, bAddr + (uint32_t)(c & 1)*BBYTES, acc);
        __syncthreads();

        if (c + 2 < 12) {
            int nc = c + 2;
            load_w512(sB, Ws[nc >> 2], nc & 3, c & 1, tid);
            CP_COMMIT();
        }

        if (kt == 3) {
            const int stage = c >> 2;
            const int r0b  = lane >> 2;
            const int colb = wn*32 + (lane & 3)*2;

            if (stage == 0) {
                #pragma unroll
                for (int mt = 0; mt < 4; mt++) {
                    int gmt = wm2*4 + mt;
                    int pt  = pbase + gmt;
                    int r0  = gmt*16 + r0b, r1 = r0 + 8;
                    const __half* qp  = g_Qh + (size_t)pt*DM;
                    const __half* k0p = g_Kh + ((size_t)(bq << 12) + idxs[r0])*DM;
                    const __half* k1p = g_Kh + ((size_t)(bq << 12) + idxs[r1])*DM;
                    #pragma unroll
                    for (int nt = 0; nt < 4; nt++) {
                        int col = colb + nt*8;
                        float2 q  = __half22float2(*(const half2*)(qp  + col));
                        float2 ka = __half22float2(*(const half2*)(k0p + col));
                        float2 kb = __half22float2(*(const half2*)(k1p + col));
                        float2 va = __half22float2(
                            *(half2*)(smemc + UOFF + (size_t)r0*APITCH_B + col*2));
                        float2 vb = __half22float2(
                            *(half2*)(smemc + UOFF + (size_t)r1*APITCH_B + col*2));
                        float p00 = acc[mt][nt][0], p01 = acc[mt][nt][1];
                        float p10 = acc[mt][nt][2], p11 = acc[mt][nt][3];
                        *(half2*)(smemc + (size_t)r0*APITCH_B + col*2) =
                            __floats2half2_rn(q.x - ka.x + p00, q.y - ka.y + p01);
                        *(half2*)(smemc + (size_t)r1*APITCH_B + col*2) =
                            __floats2half2_rn(q.x - kb.x + p10, q.y - kb.y + p11);
                        *(half2*)(smemc + UOFF + (size_t)r0*APITCH_B + col*2) =
                            __floats2half2_rn(va.x + p00, va.y + p01);
                        *(half2*)(smemc + UOFF + (size_t)r1*APITCH_B + col*2) =
                            __floats2half2_rn(vb.x + p10, vb.y + p11);
                    }
                }
            } else if (stage == 1) {
                #pragma unroll
                for (int mt = 0; mt < 4; mt++) {
                    int gmt = wm2*4 + mt;
                    int r0  = gmt*16 + r0b, r1 = r0 + 8;
                    #pragma unroll
                    for (int nt = 0; nt < 4; nt++) {
                        int col = colb + nt*8;
                        *(half2*)(smemc + (size_t)r0*APITCH_B + col*2) =
                            __floats2half2_rn(fmaxf(acc[mt][nt][0], 0.f), fmaxf(acc[mt][nt][1], 0.f));
                        *(half2*)(smemc + (size_t)r1*APITCH_B + col*2) =
                            __floats2half2_rn(fmaxf(acc[mt][nt][2], 0.f), fmaxf(acc[mt][nt][3], 0.f));
                    }
                }
            } else {
                const float sc = 0.0625f;
                #pragma unroll
                for (int mt = 0; mt < 4; mt++) {
                    int gmt = wm2*4 + mt;
                    int pt  = pbase + gmt;
                    int r0  = gmt*16 + r0b, r1 = r0 + 8;
                    #pragma unroll
                    for (int nt = 0; nt < 4; nt++) {
                        int col = colb + nt*8;
                        float2 ua = __half22float2(
                            *(half2*)(smemc + UOFF + (size_t)r0*APITCH_B + col*2));
                        float2 ub = __half22float2(
                            *(half2*)(smemc + UOFF + (size_t)r1*APITCH_B + col*2));
                        float rout[2];
                        #pragma unroll
                        for (int p = 0; p < 2; p++) {
                            float x0 = acc[mt][nt][p]     * sc;
                            float x1 = acc[mt][nt][2 + p] * sc;
                            float mx = fmaxf(x0, x1);
                            #pragma unroll
                            for (int o = 4; o < 32; o <<= 1)
                                mx = fmaxf(mx, __shfl_xor_sync(0xffffffffu, mx, o));
                            float e0 = __expf(x0 - mx), e1 = __expf(x1 - mx);
                            float s  = e0 + e1;
                            float uu0 = p ? ua.y : ua.x;
                            float uu1 = p ? ub.y : ub.x;
                            float ww = e0*uu0 + e1*uu1;
                            #pragma unroll
                            for (int o = 4; o < 32; o <<= 1) {
                                s  += __shfl_xor_sync(0xffffffffu, s , o);
                                ww += __shfl_xor_sync(0xffffffffu, ww, o);
                            }
                            rout[p] = ww / s;
                        }
                        if (lane < 4)
                            *(half2*)&g_resh[(size_t)pt*DM + col] =
                                __floats2half2_rn(rout[0], rout[1]);
                    }
                }
            }
        }
    }
}

// ---------------- finalmma: 128 rows, cp.async A, proj+LN+post+LN+residual ----
__global__ void __launch_bounds__(512) finalmma_kernel(
    const float* __restrict__ features, const float* __restrict__ b_post,
    const float* __restrict__ gdm, const float* __restrict__ bdm,
    const float* __restrict__ gdp, const float* __restrict__ bdp,
    float* __restrict__ out)
{
    extern __shared__ char smemc[];
    __shared__ float2 red[128][8];
    uint32_t sA = smem_u32(smemc);
    uint32_t sB = sA + ABYTES128;
    const int tid = threadIdx.x, lane = tid & 31, w = tid >> 5;
    const int wn = w & 7, wm2 = w >> 3;
    const int p0 = blockIdx.x * 128;

    load_w512(sB, g_Wprojh, 0, 0, tid);
    #pragma unroll
    for (int i = 0; i < 8; i++) {
        int ch = tid + i*512;
        int r = ch >> 5, c = ch & 31;
        CP16(sA + (uint32_t)r*APITCH_B + c*16, g_resh + (size_t)(p0 + r)*DM + c*8);
    }
    CP_COMMIT();
    load_w512(sB, g_Wprojh, 1, 1, tid); CP_COMMIT();

    const uint32_t aBase = sA + (uint32_t)(wm2*64 + (lane & 15))*APITCH_B + (lane >> 4)*16;
    const uint32_t bAddr = sB + (uint32_t)(wn*32 + ((lane >> 4) & 1)*8 + (lane & 7))*144
                              + ((lane >> 3) & 1)*16;
    const uint32_t bAddrP = sB + (uint32_t)(wn*8 + (lane & 7))*144 + (lane >> 3)*16;

    float acc[4][4][4];
    zero_acc4(acc);
    for (int kt = 0; kt < 4; kt++) {
        CP_WAIT1();
        __syncthreads();
        mma_tile128(aBase + kt*128, bAddr + (uint32_t)(kt & 1)*BBYTES, acc);
        __syncthreads();
        int nc = kt + 2;
        if (nc < 4) load_w512(sB, g_Wprojh, nc, kt & 1, tid);
        else        load_wpost(sB, nc - 4, kt & 1, tid);
        CP_COMMIT();
    }

    // LN(256) -> z fp16 back into A
    {
        const int r0b = lane >> 2;
        #pragma unroll
        for (int mt = 0; mt < 4; mt++) {
            int gmt = wm2*4 + mt;
            int r0 = gmt*16 + r0b, r1 = r0 + 8;
            float s0=0.f, q0=0.f, s1=0.f, q1=0.f;
            #pragma unroll
            for (int nt = 0; nt < 4; nt++) {
                float a0=acc[mt][nt][0], a1=acc[mt][nt][1];
                float a2=acc[mt][nt][2], a3=acc[mt][nt][3];
                s0 += a0+a1; q0 += a0*a0+a1*a1;
                s1 += a2+a3; q1 += a2*a2+a3*a3;
            }
            #pragma unroll
            for (int o = 1; o < 4; o <<= 1) {
                s0 += __shfl_xor_sync(~0u, s0, o); q0 += __shfl_xor_sync(~0u, q0, o);
                s1 += __shfl_xor_sync(~0u, s1, o); q1 += __shfl_xor_sync(~0u, q1, o);
            }
            if ((lane & 3) == 0) {
                red[r0][wn] = make_float2(s0, q0);
                red[r1][wn] = make_float2(s1, q1);
            }
        }
        __syncthreads();
        #pragma unroll
        for (int mt = 0; mt < 4; mt++) {
            int gmt = wm2*4 + mt;
            int r0 = gmt*16 + r0b, r1 = r0 + 8;
            float mu0, rs0, mu1, rs1;
            ln_stats8(red[r0], 1.f/DM, mu0, rs0);
            ln_stats8(red[r1], 1.f/DM, mu1, rs1);
            #pragma unroll
            for (int nt = 0; nt < 4; nt++) {
                int col = wn*32 + nt*8 + (lane & 3)*2;
                float g0 = gdm[col], g1 = gdm[col+1];
                float b0 = bdm[col], b1 = bdm[col+1];
                *(half2*)(smemc + (size_t)r0*APITCH_B + col*2) = __floats2half2_rn(
                    (acc[mt][nt][0]-mu0)*rs0*g0 + b0, (acc[mt][nt][1]-mu0)*rs0*g1 + b1);
                *(half2*)(smemc + (size_t)r1*APITCH_B + col*2) = __floats2half2_rn(
                    (acc[mt][nt][2]-mu1)*rs1*g0 + b0, (acc[mt][nt][3]-mu1)*rs1*g1 + b1);
            }
        }
    }

    // post GEMM via HMMA: chunks 4..7, N=64
    float accp[4][4];
    #pragma unroll
    for (int mt = 0; mt < 4; mt++)
        #pragma unroll
        for (int j = 0; j < 4; j++) accp[mt][j] = 0.f;

    for (int kt = 0; kt < 4; kt++) {
        int c = 4 + kt;
        if (c == 7) { CP_WAIT0(); } else { CP_WAIT1(); }
        __syncthreads();

        uint32_t ab = aBase + kt*128;
        uint32_t bb = bAddrP + (uint32_t)(c & 1)*BBYTES;
        #pragma unroll
        for (int ks2 = 0; ks2 < 2; ks2++) {
            uint32_t bfp[4];
            LDSM4(bfp[0], bfp[1], bfp[2], bfp[3], bb + ks2*64);
            #pragma unroll
            for (int sub = 0; sub < 2; sub++) {
                int ks = ks2*2 + sub;
                #pragma unroll
                for (int mt = 0; mt < 4; mt++) {
                    uint32_t af[4];
                    LDSM4(af[0], af[1], af[2], af[3], ab + mt*(16*APITCH_B) + ks*32);
                    mma16816(accp[mt], af, bfp[sub*2], bfp[sub*2 + 1]);
                }
            }
        }
        __syncthreads();
        if (kt + 2 < 4) { load_wpost(sB, kt + 2, c & 1, tid); CP_COMMIT(); }
    }

    // + b_post, LN(64), + residual
    {
        const int r0b = lane >> 2;
        const int col = wn*8 + (lane & 3)*2;
        float b0 = b_post[col], b1 = b_post[col+1];
        #pragma unroll
        for (int mt = 0; mt < 4; mt++) {
            accp[mt][0] += b0; accp[mt][1] += b1;
            accp[mt][2] += b0; accp[mt][3] += b1;
        }
        #pragma unroll
        for (int mt = 0; mt < 4; mt++) {
            int gmt = wm2*4 + mt;
            int r0 = gmt*16 + r0b, r1 = r0 + 8;
            float s0 = accp[mt][0] + accp[mt][1];
            float q0 = accp[mt][0]*accp[mt][0] + accp[mt][1]*accp[mt][1];
            float s1 = accp[mt][2] + accp[mt][3];
            float q1 = accp[mt][2]*accp[mt][2] + accp[mt][3]*accp[mt][3];
            #pragma unroll
            for (int o = 1; o < 4; o <<= 1) {
                s0 += __shfl_xor_sync(~0u, s0, o); q0 += __shfl_xor_sync(~0u, q0, o);
                s1 += __shfl_xor_sync(~0u, s1, o); q1 += __shfl_xor_sync(~0u, q1, o);
            }
            if ((lane & 3) == 0) {
                red[r0][wn] = make_float2(s0, q0);
                red[r1][wn] = make_float2(s1, q1);
            }
        }
        __syncthreads();

        float g0 = gdp[col], g1 = gdp[col+1];
        float bb0 = bdp[col], bb1 = bdp[col+1];
        #pragma unroll
        for (int mt = 0; mt < 4; mt++) {
            int gmt = wm2*4 + mt;
            int r0 = gmt*16 + r0b, r1 = r0 + 8;
            float mu0, rs0, mu1, rs1;
            ln_stats8(red[r0], 1.f/DP, mu0, rs0);
            ln_stats8(red[r1], 1.f/DP, mu1, rs1);
            size_t base0 = (size_t)(p0 + r0)*DP + col;
            size_t base1 = (size_t)(p0 + r1)*DP + col;
            float2 f0 = *(const float2*)&features[base0];
            float2 f1 = *(const float2*)&features[base1];
            *(float2*)&out[base0] = make_float2(
                (accp[mt][0]-mu0)*rs0*g0 + bb0 + f0.x,
                (accp[mt][1]-mu0)*rs0*g1 + bb1 + f0.y);
            *(float2*)&out[base1] = make_float2(
                (accp[mt][2]-mu1)*rs1*g0 + bb0 + f1.x,
                (accp[mt][3]-mu1)*rs1*g1 + bb1 + f1.y);
        }
    }
}

// ---------------- launch: full-grid kernels, knn + prepB overlapped ----------
extern "C" void kernel_launch(void* const* d_in, const int* in_sizes, int n_in,
                              void* d_out, int out_size)
{
    const float* xyz      = (const float*)d_in[0];
    const float* features = (const float*)d_in[1];
    const float* W_pre    = (const float*)d_in[2];
    const float* b_pre    = (const float*)d_in[3];
    const float* W_post   = (const float*)d_in[4];
    const float* b_post   = (const float*)d_in[5];
    const float* Wp1      = (const float*)d_in[6];
    const float* Wp2      = (const float*)d_in[7];
    const float* Wa1      = (const float*)d_in[8];
    const float* Wa2      = (const float*)d_in[9];
    const float* WQ       = (const float*)d_in[10];
    const float* WK       = (const float*)d_in[11];
    const float* WV       = (const float*)d_in[12];
    const float* Wproj    = (const float*)d_in[13];
    const float* g_dm     = (const float*)d_in[14];
    const float* b_dm     = (const float*)d_in[15];
    const float* g_dp     = (const float*)d_in[16];
    const float* b_dp     = (const float*)d_in[17];
    float* out = (float*)d_out;

    static cudaStream_t sK = nullptr, sP = nullptr;
    static cudaEvent_t evF, evK, evPB;
    if (!sK) {
        cudaStreamCreateWithFlags(&sK, cudaStreamNonBlocking);
        cudaStreamCreateWithFlags(&sP, cudaStreamNonBlocking);
        cudaEventCreateWithFlags(&evF,  cudaEventDisableTiming);
        cudaEventCreateWithFlags(&evK,  cudaEventDisableTiming);
        cudaEventCreateWithFlags(&evPB, cudaEventDisableTiming);
        cudaFuncSetAttribute(knn_kernel, cudaFuncAttributeMaxDynamicSharedMemorySize,
                             NN * (int)sizeof(float4));
        cudaFuncSetAttribute(mega_kernel,     cudaFuncAttributeMaxDynamicSharedMemorySize, MEGA_SMEM);
        cudaFuncSetAttribute(qkvmma_kernel,   cudaFuncAttributeMaxDynamicSharedMemorySize, QKV_SMEM);
        cudaFuncSetAttribute(finalmma_kernel, cudaFuncAttributeMaxDynamicSharedMemorySize, QKV_SMEM);
    }

    // fork: knn and prepB run on side streams
    cudaEventRecord(evF, 0);
    cudaStreamWaitEvent(sK, evF, 0);
    cudaStreamWaitEvent(sP, evF, 0);
    knn_kernel<<<BB*64, 256, NN*sizeof(float4), sK>>>(xyz);
    cudaEventRecord(evK, sK);
    prepB_kernel<<<256, 256, 0, sP>>>(Wproj, W_post, Wp2, Wa1, Wa2);
    cudaEventRecord(evPB, sP);

    // main: prepA -> qkvmma -> (join knn, prepB) -> mega -> finalmma
    prepA_kernel<<<256, 256>>>(W_pre, WQ, WK, WV, b_pre);
    qkvmma_kernel<<<NPTS/128, 512, QKV_SMEM>>>(features, b_pre, g_dm, b_dm);

    cudaStreamWaitEvent(0, evK, 0);
    cudaStreamWaitEvent(0, evPB, 0);
    mega_kernel<<<MTOT/128, 512, MEGA_SMEM>>>(xyz, Wp1);

    finalmma_kernel<<<NPTS/128, 512, QKV_SMEM>>>(features, b_post, g_dm, b_dm,
                                                 g_dp, b_dp, out);
}